// round 15
// baseline (speedup 1.0000x reference)
#include <cuda_runtime.h>
#include <cuda_fp16.h>
#include <cstdint>
#include <cstddef>

#define NN 8192
#define KTILE 64
#define NSPLIT 3                     // k-slices per tile: 43/43/42 KTILEs
#define ASTRIDE 144                  // bytes per smem row: 64 fp16 = 128B + 16 pad
#define A_STAGE (128 * ASTRIDE)      // 18432 (A: 128 rows)
#define B_STAGE (64 * ASTRIDE)       // 9216  (B: 64 rows)
#define STAGE_BYTES (A_STAGE + B_STAGE)   // 27648
#define STAGES 4
#define SMEM_ALLOC (STAGES * STAGE_BYTES) // 110592 -> 2 CTAs/SM
#define A_SCALE 8192.0f
#define A_INV   (1.0f / 8192.0f)

// ---------------- device-global scratch (no allocation allowed) ----------------
__device__ __half g_Acl16[(size_t)NN * NN];  // 8192*A_cl fp16 (128 MB)
__device__ __half g_Aue16[(size_t)NN * NN];  // 8192*A_ue fp16
__device__ __half g_HT[128 * NN];     // rows 0..63 = H_ue^T, 64..127 = H_cl^T
__device__ float  g_Hcl32[64 * NN];   // current-layer H_cl^T fp32 (pooling)
__device__ float  g_Xc1T[NSPLIT][64 * NN]; // (A_cl @ H_cl)^T  k-slice partials
__device__ float  g_Xc2T[NSPLIT][64 * NN]; // (A_ue @ H_ue)^T
__device__ float  g_XueT[NSPLIT][64 * NN]; // (A_ue @ H_cl)^T
__device__ float  g_pooled[64];

// ---------------- PTX helpers (sm_75/80-era: portable to plain sm_103) --------
__device__ __forceinline__ uint32_t smem_u32(const void* p) {
    uint32_t a;
    asm("{ .reg .u64 t; cvta.to.shared.u64 t, %1; cvt.u32.u64 %0, t; }" : "=r"(a) : "l"(p));
    return a;
}
__device__ __forceinline__ void cp16(uint32_t dst, const void* src) {
    asm volatile("cp.async.cg.shared.global [%0], [%1], 16;" :: "r"(dst), "l"(src));
}
#define CP_COMMIT() asm volatile("cp.async.commit_group;" ::: "memory")
#define CP_WAITP()  asm volatile("cp.async.wait_group 2;" ::: "memory")   // STAGES-2
#define CP_WAIT0()  asm volatile("cp.async.wait_group 0;" ::: "memory")

#define LDM4(d, addr) \
    asm volatile("ldmatrix.sync.aligned.m8n8.x4.shared.b16 {%0,%1,%2,%3}, [%4];" \
        : "=r"((d)[0]), "=r"((d)[1]), "=r"((d)[2]), "=r"((d)[3]) : "r"(addr))

__device__ __forceinline__ void mma16816(float* c, const uint32_t* a,
                                         uint32_t b0, uint32_t b1) {
    asm volatile(
        "mma.sync.aligned.m16n8k16.row.col.f32.f16.f16.f32 "
        "{%0,%1,%2,%3}, {%4,%5,%6,%7}, {%8,%9}, {%0,%1,%2,%3};"
        : "+f"(c[0]), "+f"(c[1]), "+f"(c[2]), "+f"(c[3])
        : "r"(a[0]), "r"(a[1]), "r"(a[2]), "r"(a[3]), "r"(b0), "r"(b1));
}

// ---------------- A fp32 -> fp16 (x8192) streaming convert --------------------
__global__ void convert_kernel(const float* __restrict__ src, __half* __restrict__ dst) {
    int i = blockIdx.x * blockDim.x + threadIdx.x;
    int stride = gridDim.x * blockDim.x;
    const float4* s4 = (const float4*)src;
    uint2* d4 = (uint2*)dst;
    const int n4 = (NN / 4) * NN;
    for (; i < n4; i += stride) {
        float4 v = s4[i];
        uint32_t lo, hi;
        asm("cvt.rn.f16x2.f32 %0, %1, %2;"
            : "=r"(lo) : "f"(v.y * A_SCALE), "f"(v.x * A_SCALE));
        asm("cvt.rn.f16x2.f32 %0, %1, %2;"
            : "=r"(hi) : "f"(v.w * A_SCALE), "f"(v.z * A_SCALE));
        d4[i] = make_uint2(lo, hi);
    }
}

// ---------------- uniform GEMM: 576 units = 192 tiles x 3 k-slices ------------
// 256 threads = 8 warps: (kw = w>>2, mw = (w>>1)&1, nw = w&1). Warp tile 64x32,
// kw splits the 4 k16-steps of each KTILE (2 each); merged via smem at the end.
__global__ void __launch_bounds__(256, 2) gemm_kernel() {
    extern __shared__ char smem[];
    const int tid  = threadIdx.x;
    const int lane = tid & 31;
    const int w    = tid >> 5;
    const int kw   = w >> 2;
    const int mw   = (w >> 1) & 1;
    const int nw   = w & 1;
    const uint32_t sbu = smem_u32(smem);

    // unit decode: u = tile * 3 + kslice
    const int u   = blockIdx.x;         // 0..575
    const int ksl = u % NSPLIT;         // k-slice 0..2
    const int t   = u / NSPLIT;         // 0..191 tile id
    const int kit0   = ksl * 43;                    // KTILE offset
    const int kiters = (ksl == 2) ? 42 : 43;        // 43+43+42 = 128
    const __half* A16;
    const __half* BT;
    float* OUT;
    int m_base;
    if (t < 64) {
        A16 = g_Acl16; m_base = t * 128;
        BT = g_HT + (size_t)64 * NN;                 // H_cl
        OUT = g_Xc1T[ksl];
    } else {
        int q = t - 64;
        A16 = g_Aue16; m_base = (q >> 1) * 128;
        BT = g_HT + (size_t)((q & 1) ? 64 : 0) * NN; // n1: H_cl, n0: H_ue
        OUT = (q & 1) ? g_XueT[ksl] : g_Xc2T[ksl];
    }
    const __half* Abase = A16 + (size_t)m_base * NN + (size_t)kit0 * KTILE;
    const __half* Bbase = BT + (size_t)kit0 * KTILE;

    // ldmatrix lane geometry
    const int lt = lane >> 3, lr = lane & 7;
    const uint32_t koff = (uint32_t)(lt >> 1) * 16;
    uint32_t a_off[4];
#pragma unroll
    for (int s = 0; s < 4; s++)
        a_off[s] = (uint32_t)(mw * 64 + s * 16 + (lt & 1) * 8 + lr) * ASTRIDE + koff;
    const uint32_t b_off0 = (uint32_t)(nw * 32 + (lt & 1) * 8 + lr) * ASTRIDE + koff;
    const uint32_t b_off1 = b_off0 + 16 * ASTRIDE;

    float c[4][4][4];
#pragma unroll
    for (int s = 0; s < 4; s++)
#pragma unroll
        for (int n = 0; n < 4; n++)
#pragma unroll
            for (int k = 0; k < 4; k++) c[s][n][k] = 0.f;

    auto load_stage = [&](int s, int kc) {
        const uint32_t as = sbu + (uint32_t)s * STAGE_BYTES;
        const uint32_t bs = as + A_STAGE;
        const __half* Ag = Abase + (size_t)kc * KTILE;
#pragma unroll
        for (int i = 0; i < 4; i++) {           // A: 128 rows x 8 chunks of 16B
            int id = tid + i * 256;
            int m = id >> 3, q = id & 7;
            cp16(as + m * ASTRIDE + q * 16, Ag + (size_t)m * NN + q * 8);
        }
        const __half* Bg = Bbase + (size_t)kc * KTILE;
#pragma unroll
        for (int i = 0; i < 2; i++) {           // B: 64 rows x 8 chunks of 16B
            int id = tid + i * 256;
            int n = id >> 3, q = id & 7;
            cp16(bs + n * ASTRIDE + q * 16, Bg + (size_t)n * NN + q * 8);
        }
    };

    for (int s = 0; s < STAGES - 1; s++) { load_stage(s, s); CP_COMMIT(); }

    for (int ki = 0; ki < kiters; ki++) {
        CP_WAITP();
        __syncthreads();       // stage ki resident CTA-wide; stage ki-1 fully read
        int nc = ki + STAGES - 1;
        if (nc < kiters) load_stage(nc & (STAGES - 1), nc);
        CP_COMMIT();

        const uint32_t as = sbu + (uint32_t)(ki & (STAGES - 1)) * STAGE_BYTES;
        const uint32_t bs = as + A_STAGE;
#pragma unroll
        for (int s2 = 0; s2 < 2; s2++) {        // this kw's two k16 steps
            const uint32_t ks = (uint32_t)kw * 64 + (uint32_t)s2 * 32;
            uint32_t a[4][4];
            LDM4(a[0], as + a_off[0] + ks);
            LDM4(a[1], as + a_off[1] + ks);
            LDM4(a[2], as + a_off[2] + ks);
            LDM4(a[3], as + a_off[3] + ks);
            uint32_t b0[4], b1[4];
            LDM4(b0, bs + b_off0 + ks);
            LDM4(b1, bs + b_off1 + ks);
#pragma unroll
            for (int s = 0; s < 4; s++) {
                mma16816(c[s][0], a[s], b0[0], b0[2]);
                mma16816(c[s][1], a[s], b0[1], b0[3]);
                mma16816(c[s][2], a[s], b1[0], b1[2]);
                mma16816(c[s][3], a[s], b1[1], b1[3]);
            }
        }
    }
    CP_WAIT0();
    __syncthreads();           // all smem reads done; reuse stage area for merge

    // intra-CTA kw merge: kw1 stores, kw0 adds. Layout [i][lane] -> conflict-free.
    float* cf = &c[0][0][0];
    float* mbuf = (float*)(smem + (size_t)(2 * mw + nw) * 8192);
    if (kw == 1) {
#pragma unroll
        for (int i = 0; i < 64; i++) mbuf[i * 32 + lane] = cf[i];
    }
    __syncthreads();
    if (kw == 0) {
#pragma unroll
        for (int i = 0; i < 64; i++) cf[i] += mbuf[i * 32 + lane];
        // transposed epilogue with descale: OUT[col][row]
#pragma unroll
        for (int s = 0; s < 4; s++)
#pragma unroll
            for (int n = 0; n < 4; n++)
#pragma unroll
                for (int k = 0; k < 4; k++) {
                    int row = m_base + mw * 64 + s * 16 + (lane >> 2) + ((k >> 1) << 3);
                    int col = nw * 32 + n * 8 + (lane & 3) * 2 + (k & 1);
                    OUT[(size_t)col * NN + row] = c[s][n][k] * A_INV;
                }
    }
}

// ---------------- layer-0 activation: relu(X[N,2] @ W[2,64] + b) combos -------
__global__ void act0_kernel(const float* __restrict__ X1, const float* __restrict__ X2,
                            const float* __restrict__ Xu,
                            const float* __restrict__ w1, const float* __restrict__ b1,
                            const float* __restrict__ w2, const float* __restrict__ b2,
                            const float* __restrict__ w3, const float* __restrict__ b3) {
    __shared__ float sw[3][2][64], sbv[3][64];
    int t = threadIdx.x;
    if (t < 128) {
        sw[0][t >> 6][t & 63] = w1[t];
        sw[1][t >> 6][t & 63] = w2[t];
        sw[2][t >> 6][t & 63] = w3[t];
    }
    if (t < 64) { sbv[0][t] = b1[t]; sbv[1][t] = b2[t]; sbv[2][t] = b3[t]; }
    __syncthreads();
    int k = blockIdx.x * 256 + t;
    float2 x1 = ((const float2*)X1)[k];
    float2 x2 = ((const float2*)X2)[k];
    float2 xu = ((const float2*)Xu)[k];
#pragma unroll 8
    for (int n = 0; n < 64; n++) {
        float h1 = fmaxf(fmaf(x1.x, sw[0][0][n], fmaf(x1.y, sw[0][1][n], sbv[0][n])), 0.f);
        float h2 = fmaxf(fmaf(x2.x, sw[1][0][n], fmaf(x2.y, sw[1][1][n], sbv[1][n])), 0.f);
        g_HT[(size_t)(64 + n) * NN + k] = __float2half_rn(h1 + h2);
        float hu = fmaxf(fmaf(xu.x, sw[2][0][n], fmaf(xu.y, sw[2][1][n], sbv[2][n])), 0.f);
        g_HT[(size_t)n * NN + k] = __float2half_rn(hu);
    }
}

// ---------------- mid-layer activation: sums 3 k-slice planes -----------------
// grid (64, 4), block 128: 128 nodes x 16 output features per CTA
__global__ void act_mid_kernel(const float* __restrict__ W1, const float* __restrict__ b1,
                               const float* __restrict__ W2, const float* __restrict__ b2,
                               const float* __restrict__ W3, const float* __restrict__ b3) {
    __shared__ float s1[64][16], s2[64][16], s3[64][16], sbv[3][16];
    int t = threadIdx.x;
    int n0 = blockIdx.y * 16;
    for (int idx = t; idx < 64 * 16; idx += 128) {
        int i = idx >> 4, j = idx & 15;
        s1[i][j] = W1[i * 64 + n0 + j];
        s2[i][j] = W2[i * 64 + n0 + j];
        s3[i][j] = W3[i * 64 + n0 + j];
    }
    if (t < 16) { sbv[0][t] = b1[n0 + t]; sbv[1][t] = b2[n0 + t]; sbv[2][t] = b3[n0 + t]; }
    __syncthreads();
    int k = blockIdx.x * 128 + t;
    float a1[16], a2[16], a3[16];
#pragma unroll
    for (int j = 0; j < 16; j++) { a1[j] = sbv[0][j]; a2[j] = sbv[1][j]; a3[j] = sbv[2][j]; }
#pragma unroll 2
    for (int i = 0; i < 64; i++) {
        size_t off = (size_t)i * NN + k;
        float x1 = g_Xc1T[0][off] + g_Xc1T[1][off] + g_Xc1T[2][off];
        float x2 = g_Xc2T[0][off] + g_Xc2T[1][off] + g_Xc2T[2][off];
        float xu = g_XueT[0][off] + g_XueT[1][off] + g_XueT[2][off];
#pragma unroll
        for (int j = 0; j < 16; j++) {
            a1[j] = fmaf(x1, s1[i][j], a1[j]);
            a2[j] = fmaf(x2, s2[i][j], a2[j]);
            a3[j] = fmaf(xu, s3[i][j], a3[j]);
        }
    }
#pragma unroll
    for (int j = 0; j < 16; j++) {
        float hcl = fmaxf(a1[j], 0.f) + fmaxf(a2[j], 0.f);
        g_HT[(size_t)(64 + n0 + j) * NN + k] = __float2half_rn(hcl);
        g_Hcl32[(size_t)(n0 + j) * NN + k] = hcl;      // fp32 copy for pooling
        g_HT[(size_t)(n0 + j) * NN + k] = __float2half_rn(fmaxf(a3[j], 0.f));
    }
}

// ---------------- pooled[n] = column sums of final H_cl (fp32) ----------------
__global__ void reduce_kernel() {
    int n = blockIdx.x, t = threadIdx.x;
    const float* row = g_Hcl32 + (size_t)n * NN;
    float s = 0.f;
    for (int k = t; k < NN; k += 256) s += row[k];
    __shared__ float sm[256];
    sm[t] = s; __syncthreads();
    for (int o = 128; o > 0; o >>= 1) { if (t < o) sm[t] += sm[t + o]; __syncthreads(); }
    if (t == 0) g_pooled[n] = sm[0];
}

// ---------------- head: relu(pooled@Qw1+Qb1)@Qw2+Qb2 -> out[0] ----------------
__global__ void head_kernel(const float* __restrict__ Qw1, const float* __restrict__ Qb1,
                            const float* __restrict__ Qw2, const float* __restrict__ Qb2,
                            float* __restrict__ out) {
    int j = threadIdx.x;  // 64 threads
    float h = Qb1[j];
    for (int i = 0; i < 64; i++) h = fmaf(g_pooled[i], Qw1[i * 64 + j], h);
    h = fmaxf(h, 0.f) * Qw2[j];
    __shared__ float sm[64];
    sm[j] = h; __syncthreads();
    for (int o = 32; o > 0; o >>= 1) { if (j < o) sm[j] += sm[j + o]; __syncthreads(); }
    if (j == 0) out[0] = sm[0] + Qb2[0];
}

extern "C" void kernel_launch(void* const* d_in, const int* in_sizes, int n_in,
                              void* d_out, int out_size) {
    const float* X1   = (const float*)d_in[0];
    const float* X2   = (const float*)d_in[1];
    const float* Xu   = (const float*)d_in[2];
    const float* Acl  = (const float*)d_in[3];
    const float* Aue  = (const float*)d_in[4];
    const float* W1w0 = (const float*)d_in[5];
    const float* W1b0 = (const float*)d_in[6];
    const float* W1w  = (const float*)d_in[7];
    const float* W1b  = (const float*)d_in[8];
    const float* W2w0 = (const float*)d_in[9];
    const float* W2b0 = (const float*)d_in[10];
    const float* W2w  = (const float*)d_in[11];
    const float* W2b  = (const float*)d_in[12];
    const float* W3w0 = (const float*)d_in[13];
    const float* W3b0 = (const float*)d_in[14];
    const float* W3w  = (const float*)d_in[15];
    const float* W3b  = (const float*)d_in[16];
    const float* Qw1  = (const float*)d_in[17];
    const float* Qb1  = (const float*)d_in[18];
    const float* Qw2  = (const float*)d_in[19];
    const float* Qb2  = (const float*)d_in[20];
    float* out = (float*)d_out;

    cudaFuncSetAttribute(gemm_kernel, cudaFuncAttributeMaxDynamicSharedMemorySize, SMEM_ALLOC);

    __half* dAcl16 = nullptr; cudaGetSymbolAddress((void**)&dAcl16, g_Acl16);
    __half* dAue16 = nullptr; cudaGetSymbolAddress((void**)&dAue16, g_Aue16);
    convert_kernel<<<4096, 256>>>(Acl, dAcl16);
    convert_kernel<<<4096, 256>>>(Aue, dAue16);
    act0_kernel<<<32, 256>>>(X1, X2, Xu, W1w0, W1b0, W2w0, W2b0, W3w0, W3b0);
    for (int l = 1; l <= 3; l++) {
        gemm_kernel<<<576, 256, SMEM_ALLOC>>>();
        size_t wo = (size_t)(l - 1) * 64 * 64;
        size_t bo = (size_t)(l - 1) * 64;
        act_mid_kernel<<<dim3(64, 4), 128>>>(W1w + wo, W1b + bo,
                                             W2w + wo, W2b + bo,
                                             W3w + wo, W3b + bo);
    }
    reduce_kernel<<<64, 256>>>();
    head_kernel<<<1, 64>>>(Qw1, Qb1, Qw2, Qb2, out);
}

// round 16
// speedup vs baseline: 1.1058x; 1.1058x over previous
#include <cuda_runtime.h>
#include <cuda_fp16.h>
#include <cstdint>
#include <cstddef>

#define NN 8192
#define KTILE 64
#define NSPLIT 3                     // k-slices per tile: 43/43/42 KTILEs
#define ASTRIDE 144                  // bytes per smem row: 64 fp16 = 128B + 16 pad
#define A_STAGE (128 * ASTRIDE)      // 18432 (A: 128 rows)
#define B_STAGE (64 * ASTRIDE)       // 9216  (B: 64 rows)
#define STAGE_BYTES (A_STAGE + B_STAGE)   // 27648
#define STAGES 4
#define SMEM_ALLOC (STAGES * STAGE_BYTES) // 110592 -> 2 CTAs/SM
#define A_SCALE 8192.0f
#define A_INV   (1.0f / 8192.0f)

// ---------------- device-global scratch (no allocation allowed) ----------------
__device__ __half g_Acl16[(size_t)NN * NN];  // 8192*A_cl fp16 (128 MB)
__device__ __half g_Aue16[(size_t)NN * NN];  // 8192*A_ue fp16
__device__ __half g_HT[128 * NN];     // rows 0..63 = H_ue^T, 64..127 = H_cl^T
__device__ float  g_Hcl32[64 * NN];   // current-layer H_cl^T fp32 (pooling)
__device__ float  g_Xc1T[NSPLIT][64 * NN]; // (A_cl @ H_cl)^T  k-slice partials
__device__ float  g_Xc2T[NSPLIT][64 * NN]; // (A_ue @ H_ue)^T
__device__ float  g_XueT[NSPLIT][64 * NN]; // (A_ue @ H_cl)^T
__device__ float  g_pooled[64];

// ---------------- PTX helpers (sm_75/80-era: portable to plain sm_103) --------
__device__ __forceinline__ uint32_t smem_u32(const void* p) {
    uint32_t a;
    asm("{ .reg .u64 t; cvta.to.shared.u64 t, %1; cvt.u32.u64 %0, t; }" : "=r"(a) : "l"(p));
    return a;
}
__device__ __forceinline__ void cp16(uint32_t dst, const void* src) {
    asm volatile("cp.async.cg.shared.global [%0], [%1], 16;" :: "r"(dst), "l"(src));
}
#define CP_COMMIT() asm volatile("cp.async.commit_group;" ::: "memory")
#define CP_WAITP()  asm volatile("cp.async.wait_group 2;" ::: "memory")   // STAGES-2
#define CP_WAIT0()  asm volatile("cp.async.wait_group 0;" ::: "memory")

#define LDM4(d, addr) \
    asm volatile("ldmatrix.sync.aligned.m8n8.x4.shared.b16 {%0,%1,%2,%3}, [%4];" \
        : "=r"((d)[0]), "=r"((d)[1]), "=r"((d)[2]), "=r"((d)[3]) : "r"(addr))

__device__ __forceinline__ void mma16816(float* c, const uint32_t* a,
                                         uint32_t b0, uint32_t b1) {
    asm volatile(
        "mma.sync.aligned.m16n8k16.row.col.f32.f16.f16.f32 "
        "{%0,%1,%2,%3}, {%4,%5,%6,%7}, {%8,%9}, {%0,%1,%2,%3};"
        : "+f"(c[0]), "+f"(c[1]), "+f"(c[2]), "+f"(c[3])
        : "r"(a[0]), "r"(a[1]), "r"(a[2]), "r"(a[3]), "r"(b0), "r"(b1));
}

// ---------------- A fp32 -> fp16 (x8192) streaming convert --------------------
// grid.y selects matrix (0: A_cl, 1: A_ue)
__global__ void convert_kernel(const float* __restrict__ s0, const float* __restrict__ s1) {
    const float* src = blockIdx.y ? s1 : s0;
    __half* dst = blockIdx.y ? g_Aue16 : g_Acl16;
    int i = blockIdx.x * blockDim.x + threadIdx.x;
    int stride = gridDim.x * blockDim.x;
    const float4* s4 = (const float4*)src;
    uint2* d4 = (uint2*)dst;
    const int n4 = (NN / 4) * NN;
    for (; i < n4; i += stride) {
        float4 v = s4[i];
        uint32_t lo, hi;
        asm("cvt.rn.f16x2.f32 %0, %1, %2;"
            : "=r"(lo) : "f"(v.y * A_SCALE), "f"(v.x * A_SCALE));
        asm("cvt.rn.f16x2.f32 %0, %1, %2;"
            : "=r"(hi) : "f"(v.w * A_SCALE), "f"(v.z * A_SCALE));
        d4[i] = make_uint2(lo, hi);
    }
}

// ---------------- uniform GEMM: 576 units = 192 tiles x 3 k-slices ------------
// 128 threads = 4 warps (mw = w>>1, nw = w&1). Warp tile 64x32, full KTILE=64
// (4 k16 steps) per warp, register double-buffered fragments, no merge phase.
__global__ void __launch_bounds__(128, 2) gemm_kernel() {
    extern __shared__ char smem[];
    const int tid  = threadIdx.x;
    const int lane = tid & 31;
    const int w    = tid >> 5;
    const int mw   = w >> 1;    // 0..1
    const int nw   = w & 1;     // 0..1
    const uint32_t sbu = smem_u32(smem);

    // unit decode: u = tile * 3 + kslice
    const int u   = blockIdx.x;         // 0..575
    const int ksl = u % NSPLIT;         // k-slice 0..2
    const int t   = u / NSPLIT;         // 0..191 tile id
    const int kit0   = ksl * 43;                    // KTILE offset
    const int kiters = (ksl == 2) ? 42 : 43;        // 43+43+42 = 128
    const __half* A16;
    const __half* BT;
    float* OUT;
    int m_base;
    if (t < 64) {
        A16 = g_Acl16; m_base = t * 128;
        BT = g_HT + (size_t)64 * NN;                 // H_cl
        OUT = g_Xc1T[ksl];
    } else {
        int q = t - 64;
        A16 = g_Aue16; m_base = (q >> 1) * 128;
        BT = g_HT + (size_t)((q & 1) ? 64 : 0) * NN; // n1: H_cl, n0: H_ue
        OUT = (q & 1) ? g_XueT[ksl] : g_Xc2T[ksl];
    }
    const __half* Abase = A16 + (size_t)m_base * NN + (size_t)kit0 * KTILE;
    const __half* Bbase = BT + (size_t)kit0 * KTILE;

    // ldmatrix lane geometry
    const int lt = lane >> 3, lr = lane & 7;
    const uint32_t koff = (uint32_t)(lt >> 1) * 16;
    uint32_t a_off[4];
#pragma unroll
    for (int s = 0; s < 4; s++)
        a_off[s] = (uint32_t)(mw * 64 + s * 16 + (lt & 1) * 8 + lr) * ASTRIDE + koff;
    const uint32_t b_off0 = (uint32_t)(nw * 32 + (lt & 1) * 8 + lr) * ASTRIDE + koff;
    const uint32_t b_off1 = b_off0 + 16 * ASTRIDE;

    float c[4][4][4];
#pragma unroll
    for (int s = 0; s < 4; s++)
#pragma unroll
        for (int n = 0; n < 4; n++)
#pragma unroll
            for (int k = 0; k < 4; k++) c[s][n][k] = 0.f;

    auto load_stage = [&](int s, int kc) {
        const uint32_t as = sbu + (uint32_t)s * STAGE_BYTES;
        const uint32_t bs = as + A_STAGE;
        const __half* Ag = Abase + (size_t)kc * KTILE;
#pragma unroll
        for (int i = 0; i < 8; i++) {           // A: 128 rows x 8 chunks of 16B
            int id = tid + i * 128;
            int m = id >> 3, q = id & 7;
            cp16(as + m * ASTRIDE + q * 16, Ag + (size_t)m * NN + q * 8);
        }
        const __half* Bg = Bbase + (size_t)kc * KTILE;
#pragma unroll
        for (int i = 0; i < 4; i++) {           // B: 64 rows x 8 chunks of 16B
            int id = tid + i * 128;
            int n = id >> 3, q = id & 7;
            cp16(bs + n * ASTRIDE + q * 16, Bg + (size_t)n * NN + q * 8);
        }
    };

    // fragment sets (double buffer)
    uint32_t aF[4][4], b0F[4], b1F[4];     // set F
    uint32_t aG[4][4], b0G[4], b1G[4];     // set G

    auto ldm_set_F = [&](uint32_t stg, uint32_t ks) {
        LDM4(aF[0], stg + a_off[0] + ks); LDM4(aF[1], stg + a_off[1] + ks);
        LDM4(aF[2], stg + a_off[2] + ks); LDM4(aF[3], stg + a_off[3] + ks);
        LDM4(b0F, stg + A_STAGE + b_off0 + ks);
        LDM4(b1F, stg + A_STAGE + b_off1 + ks);
    };
    auto ldm_set_G = [&](uint32_t stg, uint32_t ks) {
        LDM4(aG[0], stg + a_off[0] + ks); LDM4(aG[1], stg + a_off[1] + ks);
        LDM4(aG[2], stg + a_off[2] + ks); LDM4(aG[3], stg + a_off[3] + ks);
        LDM4(b0G, stg + A_STAGE + b_off0 + ks);
        LDM4(b1G, stg + A_STAGE + b_off1 + ks);
    };
    auto mma_set_F = [&]() {
#pragma unroll
        for (int s = 0; s < 4; s++) {
            mma16816(c[s][0], aF[s], b0F[0], b0F[2]);
            mma16816(c[s][1], aF[s], b0F[1], b0F[3]);
            mma16816(c[s][2], aF[s], b1F[0], b1F[2]);
            mma16816(c[s][3], aF[s], b1F[1], b1F[3]);
        }
    };
    auto mma_set_G = [&]() {
#pragma unroll
        for (int s = 0; s < 4; s++) {
            mma16816(c[s][0], aG[s], b0G[0], b0G[2]);
            mma16816(c[s][1], aG[s], b0G[1], b0G[3]);
            mma16816(c[s][2], aG[s], b1G[0], b1G[3] ^ 0u);  // placeholder fix below
            mma16816(c[s][3], aG[s], b1G[1], b1G[3]);
        }
    };
    (void)mma_set_G;  // replaced by explicit code below (avoid typo risk)

    // prologue: fill 3 stages, wait stage0, load first fragment set
    for (int s = 0; s < STAGES - 1; s++) { load_stage(s, s); CP_COMMIT(); }
    CP_WAITP();
    __syncthreads();
    ldm_set_F(sbu, 0);

    for (int ki = 0; ki < kiters; ki++) {
        const uint32_t as = sbu + (uint32_t)(ki & (STAGES - 1)) * STAGE_BYTES;
        // producer for stage ki+3 (writes slot (ki-1)%4; safe per prev-iter barrier)
        int nc = ki + STAGES - 1;
        if (nc < kiters) load_stage(nc & (STAGES - 1), nc);
        CP_COMMIT();

        // 4 k16 steps, double-buffered: F holds step0 at entry
        ldm_set_G(as, 32);      // step1
        mma_set_F();            // step0
        ldm_set_F(as, 64);      // step2
        {                       // mma step1 (set G)
#pragma unroll
            for (int s = 0; s < 4; s++) {
                mma16816(c[s][0], aG[s], b0G[0], b0G[2]);
                mma16816(c[s][1], aG[s], b0G[1], b0G[3]);
                mma16816(c[s][2], aG[s], b1G[0], b1G[2]);
                mma16816(c[s][3], aG[s], b1G[1], b1G[3]);
            }
        }
        ldm_set_G(as, 96);      // step3
        mma_set_F();            // step2
        {                       // mma step3 (set G)
#pragma unroll
            for (int s = 0; s < 4; s++) {
                mma16816(c[s][0], aG[s], b0G[0], b0G[2]);
                mma16816(c[s][1], aG[s], b0G[1], b0G[3]);
                mma16816(c[s][2], aG[s], b1G[0], b1G[2]);
                mma16816(c[s][3], aG[s], b1G[1], b1G[3]);
            }
        }

        CP_WAITP();             // stage ki+1 resident (this thread)
        __syncthreads();        // CTA-wide visibility; all reads of stage ki done
        if (ki + 1 < kiters)
            ldm_set_F(sbu + (uint32_t)((ki + 1) & (STAGES - 1)) * STAGE_BYTES, 0);
    }
    CP_WAIT0();

    // transposed epilogue with descale: OUT[col][row] (every warp owns its region)
#pragma unroll
    for (int s = 0; s < 4; s++)
#pragma unroll
        for (int n = 0; n < 4; n++)
#pragma unroll
            for (int k = 0; k < 4; k++) {
                int row = m_base + mw * 64 + s * 16 + (lane >> 2) + ((k >> 1) << 3);
                int col = nw * 32 + n * 8 + (lane & 3) * 2 + (k & 1);
                OUT[(size_t)col * NN + row] = c[s][n][k] * A_INV;
            }
}

// ---------------- layer-0 activation: relu(X[N,2] @ W[2,64] + b) combos -------
__global__ void act0_kernel(const float* __restrict__ X1, const float* __restrict__ X2,
                            const float* __restrict__ Xu,
                            const float* __restrict__ w1, const float* __restrict__ b1,
                            const float* __restrict__ w2, const float* __restrict__ b2,
                            const float* __restrict__ w3, const float* __restrict__ b3) {
    __shared__ float sw[3][2][64], sbv[3][64];
    int t = threadIdx.x;
    if (t < 128) {
        sw[0][t >> 6][t & 63] = w1[t];
        sw[1][t >> 6][t & 63] = w2[t];
        sw[2][t >> 6][t & 63] = w3[t];
    }
    if (t < 64) { sbv[0][t] = b1[t]; sbv[1][t] = b2[t]; sbv[2][t] = b3[t]; }
    __syncthreads();
    int k = blockIdx.x * 256 + t;
    float2 x1 = ((const float2*)X1)[k];
    float2 x2 = ((const float2*)X2)[k];
    float2 xu = ((const float2*)Xu)[k];
#pragma unroll 8
    for (int n = 0; n < 64; n++) {
        float h1 = fmaxf(fmaf(x1.x, sw[0][0][n], fmaf(x1.y, sw[0][1][n], sbv[0][n])), 0.f);
        float h2 = fmaxf(fmaf(x2.x, sw[1][0][n], fmaf(x2.y, sw[1][1][n], sbv[1][n])), 0.f);
        g_HT[(size_t)(64 + n) * NN + k] = __float2half_rn(h1 + h2);
        float hu = fmaxf(fmaf(xu.x, sw[2][0][n], fmaf(xu.y, sw[2][1][n], sbv[2][n])), 0.f);
        g_HT[(size_t)n * NN + k] = __float2half_rn(hu);
    }
}

// ---------------- mid-layer activation: sums 3 k-slice planes -----------------
// grid (64, 4), block 128: 128 nodes x 16 output features per CTA
__global__ void act_mid_kernel(const float* __restrict__ W1, const float* __restrict__ b1,
                               const float* __restrict__ W2, const float* __restrict__ b2,
                               const float* __restrict__ W3, const float* __restrict__ b3) {
    __shared__ float s1[64][16], s2[64][16], s3[64][16], sbv[3][16];
    int t = threadIdx.x;
    int n0 = blockIdx.y * 16;
    for (int idx = t; idx < 64 * 16; idx += 128) {
        int i = idx >> 4, j = idx & 15;
        s1[i][j] = W1[i * 64 + n0 + j];
        s2[i][j] = W2[i * 64 + n0 + j];
        s3[i][j] = W3[i * 64 + n0 + j];
    }
    if (t < 16) { sbv[0][t] = b1[n0 + t]; sbv[1][t] = b2[n0 + t]; sbv[2][t] = b3[n0 + t]; }
    __syncthreads();
    int k = blockIdx.x * 128 + t;
    float a1[16], a2[16], a3[16];
#pragma unroll
    for (int j = 0; j < 16; j++) { a1[j] = sbv[0][j]; a2[j] = sbv[1][j]; a3[j] = sbv[2][j]; }
#pragma unroll 2
    for (int i = 0; i < 64; i++) {
        size_t off = (size_t)i * NN + k;
        float x1 = g_Xc1T[0][off] + g_Xc1T[1][off] + g_Xc1T[2][off];
        float x2 = g_Xc2T[0][off] + g_Xc2T[1][off] + g_Xc2T[2][off];
        float xu = g_XueT[0][off] + g_XueT[1][off] + g_XueT[2][off];
#pragma unroll
        for (int j = 0; j < 16; j++) {
            a1[j] = fmaf(x1, s1[i][j], a1[j]);
            a2[j] = fmaf(x2, s2[i][j], a2[j]);
            a3[j] = fmaf(xu, s3[i][j], a3[j]);
        }
    }
#pragma unroll
    for (int j = 0; j < 16; j++) {
        float hcl = fmaxf(a1[j], 0.f) + fmaxf(a2[j], 0.f);
        g_HT[(size_t)(64 + n0 + j) * NN + k] = __float2half_rn(hcl);
        g_Hcl32[(size_t)(n0 + j) * NN + k] = hcl;      // fp32 copy for pooling
        g_HT[(size_t)(n0 + j) * NN + k] = __float2half_rn(fmaxf(a3[j], 0.f));
    }
}

// ---------------- pooled[n] = column sums of final H_cl (fp32) ----------------
__global__ void reduce_kernel() {
    int n = blockIdx.x, t = threadIdx.x;
    const float* row = g_Hcl32 + (size_t)n * NN;
    float s = 0.f;
    for (int k = t; k < NN; k += 256) s += row[k];
    __shared__ float sm[256];
    sm[t] = s; __syncthreads();
    for (int o = 128; o > 0; o >>= 1) { if (t < o) sm[t] += sm[t + o]; __syncthreads(); }
    if (t == 0) g_pooled[n] = sm[0];
}

// ---------------- head: relu(pooled@Qw1+Qb1)@Qw2+Qb2 -> out[0] ----------------
__global__ void head_kernel(const float* __restrict__ Qw1, const float* __restrict__ Qb1,
                            const float* __restrict__ Qw2, const float* __restrict__ Qb2,
                            float* __restrict__ out) {
    int j = threadIdx.x;  // 64 threads
    float h = Qb1[j];
    for (int i = 0; i < 64; i++) h = fmaf(g_pooled[i], Qw1[i * 64 + j], h);
    h = fmaxf(h, 0.f) * Qw2[j];
    __shared__ float sm[64];
    sm[j] = h; __syncthreads();
    for (int o = 32; o > 0; o >>= 1) { if (j < o) sm[j] += sm[j + o]; __syncthreads(); }
    if (j == 0) out[0] = sm[0] + Qb2[0];
}

extern "C" void kernel_launch(void* const* d_in, const int* in_sizes, int n_in,
                              void* d_out, int out_size) {
    const float* X1   = (const float*)d_in[0];
    const float* X2   = (const float*)d_in[1];
    const float* Xu   = (const float*)d_in[2];
    const float* Acl  = (const float*)d_in[3];
    const float* Aue  = (const float*)d_in[4];
    const float* W1w0 = (const float*)d_in[5];
    const float* W1b0 = (const float*)d_in[6];
    const float* W1w  = (const float*)d_in[7];
    const float* W1b  = (const float*)d_in[8];
    const float* W2w0 = (const float*)d_in[9];
    const float* W2b0 = (const float*)d_in[10];
    const float* W2w  = (const float*)d_in[11];
    const float* W2b  = (const float*)d_in[12];
    const float* W3w0 = (const float*)d_in[13];
    const float* W3b0 = (const float*)d_in[14];
    const float* W3w  = (const float*)d_in[15];
    const float* W3b  = (const float*)d_in[16];
    const float* Qw1  = (const float*)d_in[17];
    const float* Qb1  = (const float*)d_in[18];
    const float* Qw2  = (const float*)d_in[19];
    const float* Qb2  = (const float*)d_in[20];
    float* out = (float*)d_out;

    cudaFuncSetAttribute(gemm_kernel, cudaFuncAttributeMaxDynamicSharedMemorySize, SMEM_ALLOC);

    convert_kernel<<<dim3(2048, 2), 256>>>(Acl, Aue);
    act0_kernel<<<32, 256>>>(X1, X2, Xu, W1w0, W1b0, W2w0, W2b0, W3w0, W3b0);
    for (int l = 1; l <= 3; l++) {
        gemm_kernel<<<576, 128, SMEM_ALLOC>>>();
        size_t wo = (size_t)(l - 1) * 64 * 64;
        size_t bo = (size_t)(l - 1) * 64;
        act_mid_kernel<<<dim3(64, 4), 128>>>(W1w + wo, W1b + bo,
                                             W2w + wo, W2b + bo,
                                             W3w + wo, W3b + bo);
    }
    reduce_kernel<<<64, 256>>>();
    head_kernel<<<1, 64>>>(Qw1, Qb1, Qw2, Qb2, out);
}